// round 6
// baseline (speedup 1.0000x reference)
#include <cuda_runtime.h>
#include <cuda_bf16.h>
#include <cstdint>
#include <math.h>

#define D_MODEL 768
#define D_FF    2048
#define NE      8
#define T_TOK   2048
#define CAP     2048

// ======================= scratch (__device__ globals) =======================
__device__ int   g_count[NE];
__device__ int   g_fill[NE];
__device__ int   g_rows[NE * CAP];
__device__ float g_wts [NE * CAP];
__device__ int   g_topi[T_TOK * 2];
__device__ float g_topw[T_TOK * 2];

__device__ __align__(16) __nv_bfloat16 g_xhi[T_TOK * D_MODEL];
__device__ __align__(16) __nv_bfloat16 g_xlo[T_TOK * D_MODEL];
// weights pre-converted to hi/lo bf16, native [E][K][N] layout
__device__ __align__(16) __nv_bfloat16 g_wg_hi[(size_t)NE * D_MODEL * D_FF];
__device__ __align__(16) __nv_bfloat16 g_wg_lo[(size_t)NE * D_MODEL * D_FF];
__device__ __align__(16) __nv_bfloat16 g_wu_hi[(size_t)NE * D_MODEL * D_FF];
__device__ __align__(16) __nv_bfloat16 g_wu_lo[(size_t)NE * D_MODEL * D_FF];
__device__ __align__(16) __nv_bfloat16 g_wd_hi[(size_t)NE * D_FF * D_MODEL];
__device__ __align__(16) __nv_bfloat16 g_wd_lo[(size_t)NE * D_FF * D_MODEL];
// h = silu(g)*u, split hi/lo: [E][CAP][D_FF]
__device__ __align__(16) __nv_bfloat16 g_h_hi[(size_t)NE * CAP * D_FF];
__device__ __align__(16) __nv_bfloat16 g_h_lo[(size_t)NE * CAP * D_FF];

// ======================= helpers =======================
__device__ __forceinline__ uint32_t smem_u32(const void* p) {
    uint32_t a;
    asm("{ .reg .u64 t; cvta.to.shared.u64 t, %1; cvt.u32.u64 %0, t; }" : "=r"(a) : "l"(p));
    return a;
}
__device__ __forceinline__ void ldsm4(uint32_t (&r)[4], uint32_t addr) {
    asm volatile("ldmatrix.sync.aligned.m8n8.x4.shared.b16 {%0,%1,%2,%3}, [%4];"
                 : "=r"(r[0]), "=r"(r[1]), "=r"(r[2]), "=r"(r[3]) : "r"(addr));
}
__device__ __forceinline__ void ldsm4t(uint32_t (&r)[4], uint32_t addr) {
    asm volatile("ldmatrix.sync.aligned.m8n8.x4.trans.shared.b16 {%0,%1,%2,%3}, [%4];"
                 : "=r"(r[0]), "=r"(r[1]), "=r"(r[2]), "=r"(r[3]) : "r"(addr));
}
__device__ __forceinline__ void mma16816(float (&d)[4], const uint32_t (&a)[4],
                                         uint32_t b0, uint32_t b1) {
    asm volatile(
        "mma.sync.aligned.m16n8k16.row.col.f32.bf16.bf16.f32 "
        "{%0,%1,%2,%3}, {%4,%5,%6,%7}, {%8,%9}, {%0,%1,%2,%3};"
        : "+f"(d[0]), "+f"(d[1]), "+f"(d[2]), "+f"(d[3])
        : "r"(a[0]), "r"(a[1]), "r"(a[2]), "r"(a[3]), "r"(b0), "r"(b1));
}
#define CP16(dst, src)  asm volatile("cp.async.cg.shared.global [%0], [%1], 16;" :: "r"(dst), "l"(src))
#define CPCOMMIT()      asm volatile("cp.async.commit_group;" ::: "memory")
#define CPWAIT0()       asm volatile("cp.async.wait_group 0;" ::: "memory")

__device__ __forceinline__ uint32_t pack2(__nv_bfloat16 a, __nv_bfloat16 b) {
    __nv_bfloat162 p = __halves2bfloat162(a, b);
    return *reinterpret_cast<uint32_t*>(&p);
}

// ======================= small kernels =======================
__global__ void k_reset(float* __restrict__ out, int out_n) {
    int i = blockIdx.x * blockDim.x + threadIdx.x;
    if (i < NE) { g_count[i] = 0; g_fill[i] = 0; }
    for (int j = i; j < out_n; j += gridDim.x * blockDim.x) out[j] = 0.0f;
}

__global__ void k_router(const float* __restrict__ x, const float* __restrict__ gw) {
    int t = blockIdx.x * (blockDim.x >> 5) + (threadIdx.x >> 5);
    int lane = threadIdx.x & 31;
    if (t >= T_TOK) return;
    const float* xr = x + (size_t)t * D_MODEL;
    float acc[NE];
#pragma unroll
    for (int e = 0; e < NE; e++) acc[e] = 0.0f;
    for (int d = lane; d < D_MODEL; d += 32) {
        float xv = xr[d];
        const float* g = gw + (size_t)d * NE;
#pragma unroll
        for (int e = 0; e < NE; e++) acc[e] += xv * g[e];
    }
#pragma unroll
    for (int off = 16; off > 0; off >>= 1)
#pragma unroll
        for (int e = 0; e < NE; e++) acc[e] += __shfl_xor_sync(0xFFFFFFFFu, acc[e], off);

    if (lane == 0) {
        int i0 = 0;
#pragma unroll
        for (int e = 1; e < NE; e++) if (acc[e] > acc[i0]) i0 = e;
        int i1 = -1; float b = -1e30f;
#pragma unroll
        for (int e = 0; e < NE; e++) if (e != i0 && acc[e] > b) { b = acc[e]; i1 = e; }
        float w1 = expf(acc[i1] - acc[i0]);
        float s  = 1.0f + w1;
        g_topi[t * 2 + 0] = i0;  g_topw[t * 2 + 0] = 1.0f / s;
        g_topi[t * 2 + 1] = i1;  g_topw[t * 2 + 1] = w1 / s;
        atomicAdd(&g_count[i0], 1);
        atomicAdd(&g_count[i1], 1);
    }
}

__global__ void k_scatter() {
    int idx = blockIdx.x * blockDim.x + threadIdx.x;
    if (idx >= T_TOK * 2) return;
    int e = g_topi[idx];
    int p = atomicAdd(&g_fill[e], 1);
    g_rows[e * CAP + p] = idx >> 1;
    g_wts [e * CAP + p] = g_topw[idx];
}

__global__ void k_cvt_x(const float* __restrict__ x) {
    int i = blockIdx.x * blockDim.x + threadIdx.x;
    if (i >= T_TOK * D_MODEL) return;
    float v = x[i];
    __nv_bfloat16 hi = __float2bfloat16(v);
    g_xhi[i] = hi;
    g_xlo[i] = __float2bfloat16(v - __bfloat162float(hi));
}

// fp32 -> hi/lo bf16, vectorized float4 (n4 = n/4)
__global__ void k_cvt_w(const float* __restrict__ in, __nv_bfloat16* __restrict__ hi,
                        __nv_bfloat16* __restrict__ lo, int n4) {
    int i = blockIdx.x * blockDim.x + threadIdx.x;
    if (i >= n4) return;
    float4 f = reinterpret_cast<const float4*>(in)[i];
    float v[4] = {f.x, f.y, f.z, f.w};
    __nv_bfloat16 h[4], l[4];
#pragma unroll
    for (int j = 0; j < 4; j++) {
        h[j] = __float2bfloat16(v[j]);
        l[j] = __float2bfloat16(v[j] - __bfloat162float(h[j]));
    }
    reinterpret_cast<uint2*>(hi)[i] = make_uint2(pack2(h[0], h[1]), pack2(h[2], h[3]));
    reinterpret_cast<uint2*>(lo)[i] = make_uint2(pack2(l[0], l[1]), pack2(l[2], l[3]));
}

// ======================= HMMA GEMM kernels =======================
// Tile: M=128 x N=64, K-chunk 32. 256 threads = 8 warps in 4(m) x 2(n).
// A smem row stride 40 bf16 (80B), B 72 bf16 (144B) -> ldmatrix conflict-free, 16B-aligned.
#define SA 40
#define SB 72

// gu stage layout (bytes)
static constexpr int OFF_AH = 0;
static constexpr int OFF_AL = 10240;
static constexpr int OFF_GH = 20480;
static constexpr int OFF_GL = 25088;
static constexpr int OFF_UH = 29696;
static constexpr int OFF_UL = 34304;
static constexpr int STG_GU = 38912;
static constexpr int SMEM_GU = 2 * STG_GU;      // 77824
// down stage layout
static constexpr int OFF_BH = 20480;
static constexpr int OFF_BL = 25088;
static constexpr int STG_DN = 29696;
static constexpr int SMEM_DN = 2 * STG_DN;      // 59392

// h = silu(x@Wg) * (x@Wu)
__global__ void __launch_bounds__(256) k_hmma_gu() {
    int e   = blockIdx.z;
    int cnt = g_count[e];
    int r0  = blockIdx.y * 128;
    if (r0 >= cnt) return;
    int n0  = blockIdx.x * 64;

    extern __shared__ char smem[];
    uint32_t sb = smem_u32(smem);

    int tid = threadIdx.x, lane = tid & 31, wid = tid >> 5;
    int wm = wid >> 1, wn = wid & 1;

    // --- loader setup ---
    int arow = tid >> 1, ahalf = tid & 1;
    int slotA = r0 + arow;
    int tok = (slotA < cnt) ? g_rows[e * CAP + slotA] : 0;
    const __nv_bfloat16* pAh = g_xhi + (size_t)tok * D_MODEL + ahalf * 16;
    const __nv_bfloat16* pAl = g_xlo + (size_t)tok * D_MODEL + ahalf * 16;
    uint32_t aoff = (uint32_t)(arow * SA + ahalf * 16) * 2;

    int brow = tid >> 3, bq = tid & 7;      // 32 k-rows x 8 col-quads
    size_t bbase = (size_t)e * D_MODEL * D_FF + (size_t)brow * D_FF + n0 + bq * 8;
    const __nv_bfloat16* pGh = g_wg_hi + bbase;
    const __nv_bfloat16* pGl = g_wg_lo + bbase;
    const __nv_bfloat16* pUh = g_wu_hi + bbase;
    const __nv_bfloat16* pUl = g_wu_lo + bbase;
    uint32_t boff = (uint32_t)(brow * SB + bq * 8) * 2;

    float ag[2][4][4], au[2][4][4];
#pragma unroll
    for (int i = 0; i < 2; i++)
#pragma unroll
        for (int j = 0; j < 4; j++)
#pragma unroll
            for (int q = 0; q < 4; q++) { ag[i][j][q] = 0.0f; au[i][j][q] = 0.0f; }

    const int NC = D_MODEL / 32;            // 24

    // stage loader
    auto load_chunk = [&](int c, int s) {
        uint32_t base = sb + s * STG_GU;
        int ka = c * 32;
        size_t kb = (size_t)c * 32 * D_FF;
        CP16(base + OFF_AH + aoff,      pAh + ka);
        CP16(base + OFF_AH + aoff + 16, pAh + ka + 8);
        CP16(base + OFF_AL + aoff,      pAl + ka);
        CP16(base + OFF_AL + aoff + 16, pAl + ka + 8);
        CP16(base + OFF_GH + boff, pGh + kb);
        CP16(base + OFF_GL + boff, pGl + kb);
        CP16(base + OFF_UH + boff, pUh + kb);
        CP16(base + OFF_UL + boff, pUl + kb);
        CPCOMMIT();
    };

    load_chunk(0, 0);

    for (int c = 0; c < NC; c++) {
        CPWAIT0();
        __syncthreads();
        if (c + 1 < NC) load_chunk(c + 1, (c + 1) & 1);

        uint32_t base = sb + (c & 1) * STG_GU;
        uint32_t bAh = base + OFF_AH, bAl = base + OFF_AL;
        uint32_t bGh = base + OFF_GH, bGl = base + OFF_GL;
        uint32_t bUh = base + OFF_UH, bUl = base + OFF_UL;

#pragma unroll
        for (int kk = 0; kk < 32; kk += 16) {
            uint32_t ah[2][4], al[2][4];
#pragma unroll
            for (int mf = 0; mf < 2; mf++) {
                uint32_t ro = wm * 32 + mf * 16 + (lane & 15);
                uint32_t co = kk + (lane >> 4) * 8;
                ldsm4(ah[mf], bAh + (ro * SA + co) * 2);
                ldsm4(al[mf], bAl + (ro * SA + co) * 2);
            }
            uint32_t kr = kk + (lane & 7) + ((lane >> 4) & 1) * 8;
            uint32_t ncol = wn * 32 + ((lane >> 3) & 1) * 8;
            // ---- gate ----
            {
                uint32_t bh[4][2], bl[4][2], r4[4];
#pragma unroll
                for (int p = 0; p < 2; p++) {
                    uint32_t off = (kr * SB + ncol + p * 16) * 2;
                    ldsm4t(r4, bGh + off);
                    bh[p*2][0] = r4[0]; bh[p*2+1][0] = r4[1]; bh[p*2][1] = r4[2]; bh[p*2+1][1] = r4[3];
                    ldsm4t(r4, bGl + off);
                    bl[p*2][0] = r4[0]; bl[p*2+1][0] = r4[1]; bl[p*2][1] = r4[2]; bl[p*2+1][1] = r4[3];
                }
#pragma unroll
                for (int mf = 0; mf < 2; mf++)
#pragma unroll
                    for (int nf = 0; nf < 4; nf++) {
                        mma16816(ag[mf][nf], ah[mf], bh[nf][0], bh[nf][1]);
                        mma16816(ag[mf][nf], ah[mf], bl[nf][0], bl[nf][1]);
                        mma16816(ag[mf][nf], al[mf], bh[nf][0], bh[nf][1]);
                    }
            }
            // ---- up ----
            {
                uint32_t bh[4][2], bl[4][2], r4[4];
#pragma unroll
                for (int p = 0; p < 2; p++) {
                    uint32_t off = (kr * SB + ncol + p * 16) * 2;
                    ldsm4t(r4, bUh + off);
                    bh[p*2][0] = r4[0]; bh[p*2+1][0] = r4[1]; bh[p*2][1] = r4[2]; bh[p*2+1][1] = r4[3];
                    ldsm4t(r4, bUl + off);
                    bl[p*2][0] = r4[0]; bl[p*2+1][0] = r4[1]; bl[p*2][1] = r4[2]; bl[p*2+1][1] = r4[3];
                }
#pragma unroll
                for (int mf = 0; mf < 2; mf++)
#pragma unroll
                    for (int nf = 0; nf < 4; nf++) {
                        mma16816(au[mf][nf], ah[mf], bh[nf][0], bh[nf][1]);
                        mma16816(au[mf][nf], ah[mf], bl[nf][0], bl[nf][1]);
                        mma16816(au[mf][nf], al[mf], bh[nf][0], bh[nf][1]);
                    }
            }
        }
        __syncthreads();
    }

    // ---- epilogue: h = silu(g)*u -> split bf16 ----
    int lr = lane >> 2, lc = (lane & 3) * 2;
#pragma unroll
    for (int mf = 0; mf < 2; mf++)
#pragma unroll
        for (int half = 0; half < 2; half++) {
            int slot = r0 + wm * 32 + mf * 16 + lr + half * 8;
            if (slot >= cnt) continue;
            size_t base = ((size_t)e * CAP + slot) * D_FF + n0 + wn * 32 + lc;
#pragma unroll
            for (int nf = 0; nf < 4; nf++) {
                float g0 = ag[mf][nf][half * 2 + 0], g1 = ag[mf][nf][half * 2 + 1];
                float u0 = au[mf][nf][half * 2 + 0], u1 = au[mf][nf][half * 2 + 1];
                float h0 = (g0 / (1.0f + __expf(-g0))) * u0;
                float h1 = (g1 / (1.0f + __expf(-g1))) * u1;
                __nv_bfloat16 h0h = __float2bfloat16(h0);
                __nv_bfloat16 h1h = __float2bfloat16(h1);
                __nv_bfloat16 h0l = __float2bfloat16(h0 - __bfloat162float(h0h));
                __nv_bfloat16 h1l = __float2bfloat16(h1 - __bfloat162float(h1h));
                *(__nv_bfloat162*)(g_h_hi + base + nf * 8) = __halves2bfloat162(h0h, h1h);
                *(__nv_bfloat162*)(g_h_lo + base + nf * 8) = __halves2bfloat162(h0l, h1l);
            }
        }
}

// out[token] += gate_wt * (h @ Wd)
__global__ void __launch_bounds__(256) k_hmma_down(float* __restrict__ out) {
    int e   = blockIdx.z;
    int cnt = g_count[e];
    int r0  = blockIdx.y * 128;
    if (r0 >= cnt) return;
    int n0  = blockIdx.x * 64;

    extern __shared__ char smem[];
    uint32_t sb = smem_u32(smem);

    int tid = threadIdx.x, lane = tid & 31, wid = tid >> 5;
    int wm = wid >> 1, wn = wid & 1;

    int arow = tid >> 1, ahalf = tid & 1;
    int slotA = r0 + arow;
    int asafe = (slotA < cnt) ? slotA : 0;        // clamp: dead rows read live (finite) data
    size_t hrow = ((size_t)e * CAP + asafe) * D_FF + ahalf * 16;
    const __nv_bfloat16* pAh = g_h_hi + hrow;
    const __nv_bfloat16* pAl = g_h_lo + hrow;
    uint32_t aoff = (uint32_t)(arow * SA + ahalf * 16) * 2;

    int brow = tid >> 3, bq = tid & 7;
    size_t bbase = (size_t)e * D_FF * D_MODEL + (size_t)brow * D_MODEL + n0 + bq * 8;
    const __nv_bfloat16* pBh = g_wd_hi + bbase;
    const __nv_bfloat16* pBl = g_wd_lo + bbase;
    uint32_t boff = (uint32_t)(brow * SB + bq * 8) * 2;

    float ac[2][4][4];
#pragma unroll
    for (int i = 0; i < 2; i++)
#pragma unroll
        for (int j = 0; j < 4; j++)
#pragma unroll
            for (int q = 0; q < 4; q++) ac[i][j][q] = 0.0f;

    const int NC = D_FF / 32;               // 64

    auto load_chunk = [&](int c, int s) {
        uint32_t base = sb + s * STG_DN;
        int ka = c * 32;
        size_t kb = (size_t)c * 32 * D_MODEL;
        CP16(base + OFF_AH + aoff,      pAh + ka);
        CP16(base + OFF_AH + aoff + 16, pAh + ka + 8);
        CP16(base + OFF_AL + aoff,      pAl + ka);
        CP16(base + OFF_AL + aoff + 16, pAl + ka + 8);
        CP16(base + OFF_BH + boff, pBh + kb);
        CP16(base + OFF_BL + boff, pBl + kb);
        CPCOMMIT();
    };

    load_chunk(0, 0);

    for (int c = 0; c < NC; c++) {
        CPWAIT0();
        __syncthreads();
        if (c + 1 < NC) load_chunk(c + 1, (c + 1) & 1);

        uint32_t base = sb + (c & 1) * STG_DN;
        uint32_t bAh = base + OFF_AH, bAl = base + OFF_AL;
        uint32_t bBh = base + OFF_BH, bBl = base + OFF_BL;

#pragma unroll
        for (int kk = 0; kk < 32; kk += 16) {
            uint32_t ah[2][4], al[2][4];
#pragma unroll
            for (int mf = 0; mf < 2; mf++) {
                uint32_t ro = wm * 32 + mf * 16 + (lane & 15);
                uint32_t co = kk + (lane >> 4) * 8;
                ldsm4(ah[mf], bAh + (ro * SA + co) * 2);
                ldsm4(al[mf], bAl + (ro * SA + co) * 2);
            }
            uint32_t kr = kk + (lane & 7) + ((lane >> 4) & 1) * 8;
            uint32_t ncol = wn * 32 + ((lane >> 3) & 1) * 8;
            uint32_t bh[4][2], bl[4][2], r4[4];
#pragma unroll
            for (int p = 0; p < 2; p++) {
                uint32_t off = (kr * SB + ncol + p * 16) * 2;
                ldsm4t(r4, bBh + off);
                bh[p*2][0] = r4[0]; bh[p*2+1][0] = r4[1]; bh[p*2][1] = r4[2]; bh[p*2+1][1] = r4[3];
                ldsm4t(r4, bBl + off);
                bl[p*2][0] = r4[0]; bl[p*2+1][0] = r4[1]; bl[p*2][1] = r4[2]; bl[p*2+1][1] = r4[3];
            }
#pragma unroll
            for (int mf = 0; mf < 2; mf++)
#pragma unroll
                for (int nf = 0; nf < 4; nf++) {
                    mma16816(ac[mf][nf], ah[mf], bh[nf][0], bh[nf][1]);
                    mma16816(ac[mf][nf], ah[mf], bl[nf][0], bl[nf][1]);
                    mma16816(ac[mf][nf], al[mf], bh[nf][0], bh[nf][1]);
                }
        }
        __syncthreads();
    }

    // ---- epilogue: weighted atomic scatter-add ----
    int lr = lane >> 2, lc = (lane & 3) * 2;
#pragma unroll
    for (int mf = 0; mf < 2; mf++)
#pragma unroll
        for (int half = 0; half < 2; half++) {
            int slot = r0 + wm * 32 + mf * 16 + lr + half * 8;
            if (slot >= cnt) continue;
            int   tok = g_rows[e * CAP + slot];
            float w   = g_wts [e * CAP + slot];
            float* orow = out + (size_t)tok * D_MODEL + n0 + wn * 32 + lc;
#pragma unroll
            for (int nf = 0; nf < 4; nf++) {
                atomicAdd(&orow[nf * 8 + 0], ac[mf][nf][half * 2 + 0] * w);
                atomicAdd(&orow[nf * 8 + 1], ac[mf][nf][half * 2 + 1] * w);
            }
        }
}

// ======================= launch =======================
extern "C" void kernel_launch(void* const* d_in, const int* in_sizes, int n_in,
                              void* d_out, int out_size) {
    const float* x      = (const float*)d_in[0];   // [2,1024,768]
    const float* gate_w = (const float*)d_in[1];   // [768,8]
    const float* w_gate = (const float*)d_in[2];   // [8,768,2048]
    const float* w_up   = (const float*)d_in[3];   // [8,768,2048]
    const float* w_down = (const float*)d_in[4];   // [8,2048,768]
    float* out = (float*)d_out;

    cudaFuncSetAttribute(k_hmma_gu,   cudaFuncAttributeMaxDynamicSharedMemorySize, SMEM_GU);
    cudaFuncSetAttribute(k_hmma_down, cudaFuncAttributeMaxDynamicSharedMemorySize, SMEM_DN);

    k_reset<<<512, 256>>>(out, out_size);
    k_router<<<T_TOK / 8, 256>>>(x, gate_w);
    k_scatter<<<(T_TOK * 2 + 255) / 256, 256>>>();
    k_cvt_x<<<(T_TOK * D_MODEL + 255) / 256, 256>>>(x);

    {   // weight pre-convert fp32 -> hi/lo bf16 (native layout)
        int n4 = NE * D_MODEL * D_FF / 4;
        int gsz = (n4 + 255) / 256;
        __nv_bfloat16 *wg_hi, *wg_lo, *wu_hi, *wu_lo, *wd_hi, *wd_lo;
        cudaGetSymbolAddress((void**)&wg_hi, g_wg_hi);
        cudaGetSymbolAddress((void**)&wg_lo, g_wg_lo);
        cudaGetSymbolAddress((void**)&wu_hi, g_wu_hi);
        cudaGetSymbolAddress((void**)&wu_lo, g_wu_lo);
        cudaGetSymbolAddress((void**)&wd_hi, g_wd_hi);
        cudaGetSymbolAddress((void**)&wd_lo, g_wd_lo);
        k_cvt_w<<<gsz, 256>>>(w_gate, wg_hi, wg_lo, n4);
        k_cvt_w<<<gsz, 256>>>(w_up,   wu_hi, wu_lo, n4);
        k_cvt_w<<<gsz, 256>>>(w_down, wd_hi, wd_lo, n4);
    }

    {   // fused gate/up HMMA + SiLU
        dim3 grid(D_FF / 64, CAP / 128, NE);
        k_hmma_gu<<<grid, 256, SMEM_GU>>>();
    }
    {   // down HMMA + weighted scatter-add
        dim3 grid(D_MODEL / 64, CAP / 128, NE);
        k_hmma_down<<<grid, 256, SMEM_DN>>>(out);
    }
}